// round 4
// baseline (speedup 1.0000x reference)
#include <cuda_runtime.h>
#include <math.h>

#define BB   16
#define CC   256
#define HWp  4096
#define NTOT (16*256*4096)

// ---------------- device-global scratch (no allocations allowed) ----------------
__device__ float g_spatial[BB*CC];
__device__ float g_mod[BB*CC];
__device__ float g_y1[NTOT];
__device__ float g_sc[NTOT];
__device__ float g_bb[NTOT];
__device__ float g_scale1[CC], g_bias1[CC];
__device__ float g_scaleS[CC], g_biasS[CC];
__device__ float g_scale2[CC], g_bias2[CC];

__device__ __forceinline__ float silu_f(float z) {
    return z / (1.0f + expf(-z));
}

// ---------------------------------------------------------------------------
// Kernel 1: spatial_proj[b,c] = mean over HxW of depthwise 3x3 SAME conv.
// Uses inclusion-exclusion: only plane sum, boundary row/col sums, corners.
// grid = B*C blocks of 256 threads.
// ---------------------------------------------------------------------------
__global__ void k_spatial(const float* __restrict__ x, const float* __restrict__ w_ch) {
    int bc = blockIdx.x;
    const float* p = x + (size_t)bc * HWp;
    float T = 0.f, R0 = 0.f, R1 = 0.f, C0 = 0.f, C1 = 0.f;
    for (int k = threadIdx.x; k < HWp; k += 256) {
        float v = p[k];
        int i = k >> 6, j = k & 63;
        T += v;
        R0 += (i == 0)  ? v : 0.f;
        R1 += (i == 63) ? v : 0.f;
        C0 += (j == 0)  ? v : 0.f;
        C1 += (j == 63) ? v : 0.f;
    }
    __shared__ float sm[5][8];
    float vals[5] = {T, R0, R1, C0, C1};
    int lane = threadIdx.x & 31, w = threadIdx.x >> 5;
#pragma unroll
    for (int i = 0; i < 5; i++) {
        float v = vals[i];
#pragma unroll
        for (int o = 16; o; o >>= 1) v += __shfl_down_sync(0xffffffffu, v, o);
        if (lane == 0) sm[i][w] = v;
    }
    __syncthreads();
    if (threadIdx.x == 0) {
        float r[5];
#pragma unroll
        for (int i = 0; i < 5; i++) {
            float s = 0.f;
#pragma unroll
            for (int j = 0; j < 8; j++) s += sm[i][j];
            r[i] = s;
        }
        float Tt = r[0], Ra = r[1], Rb = r[2], Ca = r[3], Cb = r[4];
        float x00 = p[0], x0W = p[63], xH0 = p[63 * 64], xHW = p[4095];
        // S[ky][kx]: sum of x over the valid shifted window for tap (ky,kx)
        float S[9] = {
            Tt - Rb - Cb + xHW,  Tt - Rb,  Tt - Rb - Ca + xH0,
            Tt - Cb,             Tt,       Tt - Ca,
            Tt - Ra - Cb + x0W,  Tt - Ra,  Tt - Ra - Ca + x00
        };
        int c = bc & 255;
        const float* wc = w_ch + c * 9;
        float s = 0.f;
#pragma unroll
        for (int k = 0; k < 9; k++) s += wc[k] * S[k];
        g_spatial[bc] = s * (1.0f / 4096.0f);
    }
}

// ---------------------------------------------------------------------------
// Kernel 2: gating MLP -> g_mod[b,c]. grid = B blocks of 256 threads.
// ---------------------------------------------------------------------------
__global__ void k_gate(const float* __restrict__ dce,
                       const float* __restrict__ w_dce, const float* __restrict__ b_dce,
                       const float* __restrict__ w_sh,  const float* __restrict__ b_sh,
                       const float* __restrict__ w_ex,  const float* __restrict__ b_ex) {
    int b = blockIdx.x, t = threadIdx.x;
    __shared__ float pooled[128], ms[256], hs[128];
    if (t < 128) {
        const float* dp = dce + b * 100 * 128 + t;
        float s = 0.f;
        for (int l = 0; l < 100; l++) s += dp[l * 128];
        pooled[t] = s * (1.0f / 100.0f);
    }
    __syncthreads();
    {
        const float* wr = w_dce + t * 128;
        float s = b_dce[t];
#pragma unroll 8
        for (int k = 0; k < 128; k++) s += pooled[k] * wr[k];
        ms[t] = s * g_spatial[b * 256 + t];
    }
    __syncthreads();
    if (t < 128) {
        const float* wr = w_sh + t * 256;
        float s = b_sh[t];
#pragma unroll 8
        for (int k = 0; k < 256; k++) s += ms[k] * wr[k];
        hs[t] = fmaxf(s, 0.f);
    }
    __syncthreads();
    {
        const float* wr = w_ex + t * 128;
        float s = b_ex[t];
#pragma unroll 8
        for (int k = 0; k < 128; k++) s += hs[k] * wr[k];
        g_mod[b * 256 + t] = 1.0f / (1.0f + expf(-s));
    }
}

// ---------------------------------------------------------------------------
// Kernel 3: conv1 3x3 SAME, 256->256, input xm = x * mod (computed on the fly).
// CTA tile: 32x32 spatial x 16 output channels for one batch.
// Thread micro-tile: 8 co x (2x4) px -> 64 accumulators.
// grid = (4 spatial tiles, 16 co groups, 16 batch), 256 threads.
// ---------------------------------------------------------------------------
__global__ __launch_bounds__(256, 2) void k_conv1(const float* __restrict__ x,
                                                  const float* __restrict__ w1) {
    __shared__ float tile[34][35];   // input halo tile, pad to 35 for <=2-way conflicts
    __shared__ float wsm[16][9];

    int b   = blockIdx.z;
    int cog = blockIdx.y;                    // co base = cog*16
    int tr0 = (blockIdx.x >> 1) * 32;
    int tc0 = (blockIdx.x & 1) * 32;
    int tid = threadIdx.x;
    int co_sub = tid >> 7;                   // 0/1 -> 8-co half
    int ptid   = tid & 127;
    int lr = (ptid >> 3) * 2;                // 0..30 step 2
    int lc = (ptid & 7) * 4;                 // 0..28 step 4

    float acc[8][2][4];
#pragma unroll
    for (int o = 0; o < 8; o++)
#pragma unroll
        for (int pr = 0; pr < 2; pr++)
#pragma unroll
            for (int pc = 0; pc < 4; pc++) acc[o][pr][pc] = 0.f;

    for (int ci = 0; ci < 256; ci++) {
        __syncthreads();
        float modv = g_mod[b * 256 + ci];
        const float* xp = x + ((size_t)(b * 256 + ci)) * HWp;
#pragma unroll
        for (int it = 0; it < 5; it++) {
            int idx = tid + it * 256;
            if (idx < 34 * 34) {
                int r = idx / 34, cc = idx - r * 34;
                int gr = tr0 - 1 + r, gc = tc0 - 1 + cc;
                float v = 0.f;
                if ((unsigned)gr < 64u && (unsigned)gc < 64u) v = xp[gr * 64 + gc] * modv;
                tile[r][cc] = v;
            }
        }
        if (tid < 144) {
            int o = tid / 9, k = tid - o * 9;
            wsm[o][k] = w1[((size_t)(cog * 16 + o) * 256 + ci) * 9 + k];
        }
        __syncthreads();

        float xin[4][6];
#pragma unroll
        for (int r = 0; r < 4; r++)
#pragma unroll
            for (int c2 = 0; c2 < 6; c2++) xin[r][c2] = tile[lr + r][lc + c2];

#pragma unroll
        for (int o = 0; o < 8; o++) {
            float wv[9];
#pragma unroll
            for (int k = 0; k < 9; k++) wv[k] = wsm[co_sub * 8 + o][k];
#pragma unroll
            for (int pr = 0; pr < 2; pr++)
#pragma unroll
                for (int pc = 0; pc < 4; pc++) {
                    float s = acc[o][pr][pc];
#pragma unroll
                    for (int ky = 0; ky < 3; ky++)
#pragma unroll
                        for (int kx = 0; kx < 3; kx++)
                            s += wv[ky * 3 + kx] * xin[pr + ky][pc + kx];
                    acc[o][pr][pc] = s;
                }
        }
    }

#pragma unroll
    for (int o = 0; o < 8; o++) {
        int co = cog * 16 + co_sub * 8 + o;
#pragma unroll
        for (int pr = 0; pr < 2; pr++) {
            float4 v = make_float4(acc[o][pr][0], acc[o][pr][1], acc[o][pr][2], acc[o][pr][3]);
            *(float4*)&g_y1[((size_t)(b * 256 + co)) * HWp + (tr0 + lr + pr) * 64 + tc0 + lc] = v;
        }
    }
}

// ---------------------------------------------------------------------------
// Kernel 4: 1x1 conv as per-batch SGEMM, C_out x HW = W(256x256) @ in(256xHW).
// MODE 0: in = x * mod        -> out = g_sc   (shortcut conv)
// MODE 1: in = silu(bn1(y1))  -> out = g_bb   (conv2)
// Tile 64co x 64px, K-chunks of 16; 4x4 micro-tile; float4 smem IO.
// grid = (64 px tiles, 4 co tiles, 16 batch), 256 threads.
// ---------------------------------------------------------------------------
template <int MODE>
__global__ __launch_bounds__(256) void k_gemm1x1(const float* __restrict__ xin,
                                                 const float* __restrict__ w) {
    __shared__ float Asm[16][68];
    __shared__ float Bsm[16][68];
    int b   = blockIdx.z;
    int cob = blockIdx.y * 64;
    int pxb = blockIdx.x * 64;
    int tid = threadIdx.x;
    const float* in = (MODE == 0) ? xin : g_y1;
    float* out      = (MODE == 0) ? g_sc : g_bb;

    float acc[4][4];
#pragma unroll
    for (int i = 0; i < 4; i++)
#pragma unroll
        for (int j = 0; j < 4; j++) acc[i][j] = 0.f;

    int trow = tid >> 4;   // co quad (16)
    int tcol = tid & 15;   // px quad (16)

    for (int kb = 0; kb < 256; kb += 16) {
        __syncthreads();
        {   // weights: Asm[k][co]
            int col = tid & 63, kq = tid >> 6;
            float4 wv = *(const float4*)&w[(size_t)(cob + col) * 256 + kb + kq * 4];
            Asm[kq * 4 + 0][col] = wv.x;
            Asm[kq * 4 + 1][col] = wv.y;
            Asm[kq * 4 + 2][col] = wv.z;
            Asm[kq * 4 + 3][col] = wv.w;
        }
        {   // activations: Bsm[k][px] with fused pre-op
            int k = tid >> 4, p4 = (tid & 15) * 4;
            int ch = kb + k;
            float4 v = *(const float4*)&in[((size_t)(b * 256 + ch)) * HWp + pxb + p4];
            if (MODE == 0) {
                float mm = g_mod[b * 256 + ch];
                v.x *= mm; v.y *= mm; v.z *= mm; v.w *= mm;
            } else {
                float s = g_scale1[ch], t = g_bias1[ch];
                v.x = silu_f(fmaf(s, v.x, t));
                v.y = silu_f(fmaf(s, v.y, t));
                v.z = silu_f(fmaf(s, v.z, t));
                v.w = silu_f(fmaf(s, v.w, t));
            }
            *(float4*)&Bsm[k][p4] = v;
        }
        __syncthreads();
#pragma unroll
        for (int k = 0; k < 16; k++) {
            float4 a  = *(const float4*)&Asm[k][trow * 4];
            float4 bv = *(const float4*)&Bsm[k][tcol * 4];
            acc[0][0] += a.x * bv.x; acc[0][1] += a.x * bv.y; acc[0][2] += a.x * bv.z; acc[0][3] += a.x * bv.w;
            acc[1][0] += a.y * bv.x; acc[1][1] += a.y * bv.y; acc[1][2] += a.y * bv.z; acc[1][3] += a.y * bv.w;
            acc[2][0] += a.z * bv.x; acc[2][1] += a.z * bv.y; acc[2][2] += a.z * bv.z; acc[2][3] += a.z * bv.w;
            acc[3][0] += a.w * bv.x; acc[3][1] += a.w * bv.y; acc[3][2] += a.w * bv.z; acc[3][3] += a.w * bv.w;
        }
    }
#pragma unroll
    for (int i = 0; i < 4; i++) {
        float4 v = make_float4(acc[i][0], acc[i][1], acc[i][2], acc[i][3]);
        *(float4*)&out[((size_t)(b * 256 + cob + trow * 4 + i)) * HWp + pxb + tcol * 4] = v;
    }
}

// ---------------------------------------------------------------------------
// Kernel 5: per-channel BN stats (training mode, biased var) -> scale/bias.
// mode 0: y1 -> (scale1,bias1); 1: sc -> (scaleS,biasS); 2: bb -> (scale2,bias2)
// grid = 256 channels, 256 threads.
// ---------------------------------------------------------------------------
__global__ void k_stats(int mode, const float* __restrict__ g, const float* __restrict__ be) {
    const float* buf = (mode == 0) ? g_y1 : ((mode == 1) ? g_sc : g_bb);
    int c = blockIdx.x;
    float s = 0.f, s2 = 0.f;
    for (int b = 0; b < 16; b++) {
        const float4* p = (const float4*)(buf + ((size_t)(b * 256 + c)) * HWp);
        for (int i = threadIdx.x; i < 1024; i += 256) {
            float4 v = p[i];
            s  += v.x + v.y + v.z + v.w;
            s2 += v.x * v.x + v.y * v.y + v.z * v.z + v.w * v.w;
        }
    }
    int lane = threadIdx.x & 31, w = threadIdx.x >> 5;
#pragma unroll
    for (int o = 16; o; o >>= 1) {
        s  += __shfl_down_sync(0xffffffffu, s, o);
        s2 += __shfl_down_sync(0xffffffffu, s2, o);
    }
    __shared__ float sm[2][8];
    if (lane == 0) { sm[0][w] = s; sm[1][w] = s2; }
    __syncthreads();
    if (threadIdx.x == 0) {
        float S = 0.f, S2 = 0.f;
#pragma unroll
        for (int j = 0; j < 8; j++) { S += sm[0][j]; S2 += sm[1][j]; }
        const float inv_n = 1.0f / (16.0f * 4096.0f);
        float mean = S * inv_n;
        float var  = S2 * inv_n - mean * mean;
        float sc = g[c] * rsqrtf(var + 1e-5f);
        float bi = be[c] - mean * sc;
        if (mode == 0)      { g_scale1[c] = sc; g_bias1[c] = bi; }
        else if (mode == 1) { g_scaleS[c] = sc; g_biasS[c] = bi; }
        else                { g_scale2[c] = sc; g_bias2[c] = bi; }
    }
}

// ---------------------------------------------------------------------------
// Kernel 6: out = silu( bn2(bb) + bns(sc) ), elementwise float4.
// ---------------------------------------------------------------------------
__global__ void k_final(float* __restrict__ out) {
    int i4 = blockIdx.x * 256 + threadIdx.x;
    if (i4 >= NTOT / 4) return;
    int idx = i4 * 4;
    int c = (idx >> 12) & 255;
    float s2 = g_scale2[c], b2 = g_bias2[c];
    float ss = g_scaleS[c], bs = g_biasS[c];
    float4 vb = ((const float4*)g_bb)[i4];
    float4 vs = ((const float4*)g_sc)[i4];
    float4 r;
    r.x = silu_f(fmaf(s2, vb.x, b2) + fmaf(ss, vs.x, bs));
    r.y = silu_f(fmaf(s2, vb.y, b2) + fmaf(ss, vs.y, bs));
    r.z = silu_f(fmaf(s2, vb.z, b2) + fmaf(ss, vs.z, bs));
    r.w = silu_f(fmaf(s2, vb.w, b2) + fmaf(ss, vs.w, bs));
    ((float4*)out)[i4] = r;
}

// ---------------------------------------------------------------------------
extern "C" void kernel_launch(void* const* d_in, const int* in_sizes, int n_in,
                              void* d_out, int out_size) {
    const float* x     = (const float*)d_in[0];
    const float* dce   = (const float*)d_in[1];
    const float* w_dce = (const float*)d_in[2];
    const float* b_dce = (const float*)d_in[3];
    const float* w_ch  = (const float*)d_in[4];
    const float* w_sh  = (const float*)d_in[5];
    const float* b_sh  = (const float*)d_in[6];
    const float* w_ex  = (const float*)d_in[7];
    const float* b_ex  = (const float*)d_in[8];
    const float* w1    = (const float*)d_in[9];
    const float* g1    = (const float*)d_in[10];
    const float* be1   = (const float*)d_in[11];
    const float* w2    = (const float*)d_in[12];
    const float* g2    = (const float*)d_in[13];
    const float* be2   = (const float*)d_in[14];
    const float* wsc   = (const float*)d_in[15];
    const float* gs    = (const float*)d_in[16];
    const float* bes   = (const float*)d_in[17];

    k_spatial<<<4096, 256>>>(x, w_ch);
    k_gate<<<16, 256>>>(dce, w_dce, b_dce, w_sh, b_sh, w_ex, b_ex);
    k_conv1<<<dim3(4, 16, 16), 256>>>(x, w1);
    k_gemm1x1<0><<<dim3(64, 4, 16), 256>>>(x, wsc);       // shortcut 1x1 on xm
    k_stats<<<256, 256>>>(0, g1, be1);                    // bn1 params from y1
    k_stats<<<256, 256>>>(1, gs, bes);                    // bns params from sc
    k_gemm1x1<1><<<dim3(64, 4, 16), 256>>>(nullptr, w2);  // conv2 on silu(bn1(y1))
    k_stats<<<256, 256>>>(2, g2, be2);                    // bn2 params from bb
    k_final<<<16384, 256>>>((float*)d_out);
}

// round 8
// speedup vs baseline: 3.2655x; 3.2655x over previous
#include <cuda_runtime.h>
#include <math.h>
#include <stdint.h>

#define BB   16
#define CC   256
#define HWp  4096
#define NTOT (16*256*4096)

// ---------------- device-global scratch (no allocations allowed) ----------------
__device__ float g_spatial[BB*CC];
__device__ float g_mod[BB*CC];
__device__ float g_w1t[9*256*256];   // conv1 weights transposed+rounded: [tap][co][ci]
__device__ float g_wscr[256*256];    // rounded shortcut weights [co][ci]
__device__ float g_w2r[256*256];     // rounded conv2 weights   [co][ci]
__device__ float g_xm[NTOT];         // rna(x * mod)
__device__ float g_a1[NTOT];         // rna(silu(bn1(y1)))
__device__ float g_y1[NTOT];
__device__ float g_sc[NTOT];
__device__ float g_bb[NTOT];
__device__ float g_scale1[CC], g_bias1[CC];
__device__ float g_scaleS[CC], g_biasS[CC];
__device__ float g_scale2[CC], g_bias2[CC];

__device__ __forceinline__ float silu_f(float z) {
    return z / (1.0f + __expf(-z));
}
__device__ __forceinline__ float tf32r(float x) {
    unsigned u;
    asm("cvt.rna.tf32.f32 %0, %1;" : "=r"(u) : "f"(x));
    return __uint_as_float(u);
}
__device__ __forceinline__ uint32_t smem_u32(const void* p) {
    uint32_t a;
    asm("{ .reg .u64 t; cvta.to.shared.u64 t, %1; cvt.u32.u64 %0, t; }" : "=r"(a) : "l"(p));
    return a;
}

#define CP16(dst, src) \
    asm volatile("cp.async.ca.shared.global [%0], [%1], 16;" :: "r"(dst), "l"(src) : "memory")
#define CP4Z(dst, src, sz) \
    asm volatile("cp.async.ca.shared.global [%0], [%1], 4, %2;" :: "r"(dst), "l"(src), "r"(sz) : "memory")
#define CP_COMMIT() asm volatile("cp.async.commit_group;" ::: "memory")
#define CP_WAIT(n)  asm volatile("cp.async.wait_group %0;" :: "n"(n) : "memory")

#define MMA8(d, a, b0, b1) \
    asm volatile("mma.sync.aligned.m16n8k8.row.col.f32.tf32.tf32.f32 " \
                 "{%0,%1,%2,%3}, {%4,%5,%6,%7}, {%8,%9}, {%0,%1,%2,%3};" \
                 : "+f"((d)[0]), "+f"((d)[1]), "+f"((d)[2]), "+f"((d)[3]) \
                 : "r"((a)[0]), "r"((a)[1]), "r"((a)[2]), "r"((a)[3]), "r"(b0), "r"(b1))

// ---------------------------------------------------------------------------
// Kernel 0a: conv1 weight transpose+round w1[co][ci][tap] -> g_w1t[tap][co][ci]
// ---------------------------------------------------------------------------
__global__ void k_wt(const float* __restrict__ w1) {
    int i = blockIdx.x * 256 + threadIdx.x;
    if (i >= 9 * 256 * 256) return;
    int tap = i % 9;
    int rest = i / 9;
    int ci = rest & 255;
    int co = rest >> 8;
    g_w1t[((tap << 8) + co) * 256 + ci] = tf32r(w1[i]);
}

// Kernel 0b: round 1x1 weights
__global__ void k_wround(const float* __restrict__ wsc, const float* __restrict__ w2) {
    int i = blockIdx.x * 256 + threadIdx.x;
    if (i >= 256 * 256) return;
    g_wscr[i] = tf32r(wsc[i]);
    g_w2r[i]  = tf32r(w2[i]);
}

// ---------------------------------------------------------------------------
// Kernel 1: spatial_proj via inclusion-exclusion (exact)
// ---------------------------------------------------------------------------
__global__ void k_spatial(const float* __restrict__ x, const float* __restrict__ w_ch) {
    int bc = blockIdx.x;
    const float* p = x + (size_t)bc * HWp;
    float T = 0.f, R0 = 0.f, R1 = 0.f, C0 = 0.f, C1 = 0.f;
    for (int k = threadIdx.x; k < HWp; k += 256) {
        float v = p[k];
        int i = k >> 6, j = k & 63;
        T += v;
        R0 += (i == 0)  ? v : 0.f;
        R1 += (i == 63) ? v : 0.f;
        C0 += (j == 0)  ? v : 0.f;
        C1 += (j == 63) ? v : 0.f;
    }
    __shared__ float sm[5][8];
    float vals[5] = {T, R0, R1, C0, C1};
    int lane = threadIdx.x & 31, w = threadIdx.x >> 5;
#pragma unroll
    for (int i = 0; i < 5; i++) {
        float v = vals[i];
#pragma unroll
        for (int o = 16; o; o >>= 1) v += __shfl_down_sync(0xffffffffu, v, o);
        if (lane == 0) sm[i][w] = v;
    }
    __syncthreads();
    if (threadIdx.x == 0) {
        float r[5];
#pragma unroll
        for (int i = 0; i < 5; i++) {
            float s = 0.f;
#pragma unroll
            for (int j = 0; j < 8; j++) s += sm[i][j];
            r[i] = s;
        }
        float Tt = r[0], Ra = r[1], Rb = r[2], Ca = r[3], Cb = r[4];
        float x00 = p[0], x0W = p[63], xH0 = p[63 * 64], xHW = p[4095];
        float S[9] = {
            Tt - Rb - Cb + xHW,  Tt - Rb,  Tt - Rb - Ca + xH0,
            Tt - Cb,             Tt,       Tt - Ca,
            Tt - Ra - Cb + x0W,  Tt - Ra,  Tt - Ra - Ca + x00
        };
        int c = bc & 255;
        const float* wc = w_ch + c * 9;
        float s = 0.f;
#pragma unroll
        for (int k = 0; k < 9; k++) s += wc[k] * S[k];
        g_spatial[bc] = s * (1.0f / 4096.0f);
    }
}

// ---------------------------------------------------------------------------
// Kernel 2: gating MLP -> g_mod (exact)
// ---------------------------------------------------------------------------
__global__ void k_gate(const float* __restrict__ dce,
                       const float* __restrict__ w_dce, const float* __restrict__ b_dce,
                       const float* __restrict__ w_sh,  const float* __restrict__ b_sh,
                       const float* __restrict__ w_ex,  const float* __restrict__ b_ex) {
    int b = blockIdx.x, t = threadIdx.x;
    __shared__ float pooled[128], ms[256], hs[128];
    if (t < 128) {
        const float* dp = dce + b * 100 * 128 + t;
        float s = 0.f;
        for (int l = 0; l < 100; l++) s += dp[l * 128];
        pooled[t] = s * (1.0f / 100.0f);
    }
    __syncthreads();
    {
        const float* wr = w_dce + t * 128;
        float s = b_dce[t];
#pragma unroll 8
        for (int k = 0; k < 128; k++) s += pooled[k] * wr[k];
        ms[t] = s * g_spatial[b * 256 + t];
    }
    __syncthreads();
    if (t < 128) {
        const float* wr = w_sh + t * 256;
        float s = b_sh[t];
#pragma unroll 8
        for (int k = 0; k < 256; k++) s += ms[k] * wr[k];
        hs[t] = fmaxf(s, 0.f);
    }
    __syncthreads();
    {
        const float* wr = w_ex + t * 128;
        float s = b_ex[t];
#pragma unroll 8
        for (int k = 0; k < 128; k++) s += hs[k] * wr[k];
        g_mod[b * 256 + t] = 1.0f / (1.0f + expf(-s));
    }
}

// ---------------------------------------------------------------------------
// Kernel 3a: g_xm = rna(x * mod)   (float4 elementwise)
// ---------------------------------------------------------------------------
__global__ void k_xm(const float* __restrict__ x) {
    int i4 = blockIdx.x * 256 + threadIdx.x;
    if (i4 >= NTOT / 4) return;
    int idx = i4 * 4;
    int c = (idx >> 12) & 255;
    int b = idx >> 20;
    float m = g_mod[b * 256 + c];
    float4 v = ((const float4*)x)[i4];
    v.x = tf32r(v.x * m); v.y = tf32r(v.y * m);
    v.z = tf32r(v.z * m); v.w = tf32r(v.w * m);
    ((float4*)g_xm)[i4] = v;
}

// Kernel 3b: g_a1 = rna(silu(bn1(y1)))
__global__ void k_a1(void) {
    int i4 = blockIdx.x * 256 + threadIdx.x;
    if (i4 >= NTOT / 4) return;
    int idx = i4 * 4;
    int c = (idx >> 12) & 255;
    float s = g_scale1[c], t = g_bias1[c];
    float4 v = ((const float4*)g_y1)[i4];
    v.x = tf32r(silu_f(fmaf(s, v.x, t)));
    v.y = tf32r(silu_f(fmaf(s, v.y, t)));
    v.z = tf32r(silu_f(fmaf(s, v.z, t)));
    v.w = tf32r(silu_f(fmaf(s, v.w, t)));
    ((float4*)g_a1)[i4] = v;
}

// ---------------------------------------------------------------------------
// Tensor kernel: tf32 warp-MMA implicit GEMM.
//   D[px(128)][co(128)] = sum_k A[px][k] * W[co][k]
//   KIND 0: conv1  (A=g_xm, im2col 9 taps, W=g_w1t, out=g_y1)
//   KIND 1: shortcut 1x1 (A=g_xm, W=g_wscr, out=g_sc)
//   KIND 2: conv2 1x1    (A=g_a1, W=g_w2r,  out=g_bb)
// grid = (32 px tiles, 2 co tiles, 16 batch), 256 threads (8 warps 4m x 2n).
// Smem: double-buffered A[32k][136px-pad] + W[128co][36k-pad], cp.async staged.
// ---------------------------------------------------------------------------
#define PA 136
#define PB 36
#define ABUF (32*PA)
#define BBUF2 (128*PB)
#define BUFF (ABUF + BBUF2)
#define SMEM_DYN (2 * BUFF * 4)

template <int KIND>
__global__ __launch_bounds__(256, 2) void k_tmma(void) {
    extern __shared__ float smf[];
    const uint32_t sbase = smem_u32(smf);
    const int tid = threadIdx.x;
    const int b = blockIdx.z;
    const int cob = blockIdx.y * 128;
    const int pxb = blockIdx.x * 128;

    const float* in   = (KIND == 2) ? g_a1 : g_xm;
    const float* wsrc = (KIND == 0) ? g_w1t : ((KIND == 1) ? g_wscr : g_w2r);
    float* out        = (KIND == 0) ? g_y1 : ((KIND == 1) ? g_sc : g_bb);
    const int NTAPS = (KIND == 0) ? 9 : 1;
    const int NCH = NTAPS * 8;

    const int l = tid & 31, wid = tid >> 5;
    const int warp_m = wid & 3, warp_n = wid >> 2;
    const int g = l >> 2, tg = l & 3;

    float d[2][8][4];
#pragma unroll
    for (int mt = 0; mt < 2; mt++)
#pragma unroll
        for (int nt = 0; nt < 8; nt++)
#pragma unroll
            for (int j = 0; j < 4; j++) d[mt][nt][j] = 0.f;

    // ---- staging (cp.async) ----
    auto stage = [&](int cc, int s) {
        uint32_t aB = sbase + (uint32_t)(s * BUFF) * 4u;
        uint32_t bB = aB + ABUF * 4u;
        int tap = (NTAPS == 9) ? (cc >> 3) : 0;
        int kb  = ((NTAPS == 9) ? (cc & 7) : cc) * 32;
        if (KIND == 0) {
            int dy = tap / 3 - 1, dx = tap % 3 - 1;
            const float* basep = in + ((size_t)(b * 256 + kb) << 12) + dy * 64 + dx;
#pragma unroll
            for (int it = 0; it < 16; it++) {
                int item = it * 256 + tid;
                int k = item >> 7, px = item & 127;
                int pxg = pxb + px;
                int rr = (pxg >> 6) + dy, cc2 = (pxg & 63) + dx;
                unsigned ok = (((unsigned)rr < 64u) && ((unsigned)cc2 < 64u)) ? 4u : 0u;
                CP4Z(aB + (uint32_t)(k * PA + px) * 4u, basep + ((size_t)k << 12) + pxg, ok);
            }
        } else {
            const float* basep = in + ((size_t)(b * 256 + kb) << 12) + pxb;
#pragma unroll
            for (int it = 0; it < 4; it++) {
                int item = it * 256 + tid;
                int k = item >> 5, q = item & 31;
                CP16(aB + (uint32_t)(k * PA + q * 4) * 4u, basep + ((size_t)k << 12) + q * 4);
            }
        }
        {
            const float* wp = wsrc + ((size_t)(((NTAPS == 9) ? tap * 256 : 0) + cob)) * 256 + kb;
#pragma unroll
            for (int it = 0; it < 4; it++) {
                int item = it * 256 + tid;
                int col = item >> 3, kq = item & 7;
                CP16(bB + (uint32_t)(col * PB + kq * 4) * 4u, wp + (size_t)col * 256 + kq * 4);
            }
        }
    };

    stage(0, 0);
    CP_COMMIT();

    for (int ch = 0; ch < NCH; ch++) {
        if (ch + 1 < NCH) {
            stage(ch + 1, (ch + 1) & 1);
            CP_COMMIT();
            CP_WAIT(1);
        } else {
            CP_WAIT(0);
        }
        __syncthreads();   // chunk ch visible to all warps

        const float* As = smf + (ch & 1) * BUFF;
        const float* Bs = As + ABUF;
#pragma unroll
        for (int kt = 0; kt < 4; kt++) {
            int kk = kt * 8 + tg;
            uint32_t a[2][4];
#pragma unroll
            for (int mt = 0; mt < 2; mt++) {
                int m0 = warp_m * 32 + mt * 16 + g;
                a[mt][0] = __float_as_uint(As[kk * PA + m0]);
                a[mt][1] = __float_as_uint(As[kk * PA + m0 + 8]);
                a[mt][2] = __float_as_uint(As[(kk + 4) * PA + m0]);
                a[mt][3] = __float_as_uint(As[(kk + 4) * PA + m0 + 8]);
            }
#pragma unroll
            for (int nt = 0; nt < 8; nt++) {
                int n0 = warp_n * 64 + nt * 8 + g;
                uint32_t b0 = __float_as_uint(Bs[n0 * PB + kk]);
                uint32_t b1 = __float_as_uint(Bs[n0 * PB + kk + 4]);
                MMA8(d[0][nt], a[0], b0, b1);
                MMA8(d[1][nt], a[1], b0, b1);
            }
        }
        __syncthreads();   // all warps done with buffer before next overwrite
    }

    // ---- epilogue ----
#pragma unroll
    for (int mt = 0; mt < 2; mt++) {
        int px = pxb + warp_m * 32 + mt * 16 + g;
#pragma unroll
        for (int nt = 0; nt < 8; nt++) {
            int co = cob + warp_n * 64 + nt * 8 + tg * 2;
            float* o = out + (((size_t)(b * 256 + co)) << 12) + px;
            o[0]    = d[mt][nt][0];
            o[4096] = d[mt][nt][1];
            o[8]    = d[mt][nt][2];
            o[4104] = d[mt][nt][3];
        }
    }
}

// ---------------------------------------------------------------------------
// Kernel 5: per-channel BN stats (training mode, biased var) -> scale/bias.
// ---------------------------------------------------------------------------
__global__ void k_stats(int mode, const float* __restrict__ g, const float* __restrict__ be) {
    const float* buf = (mode == 0) ? g_y1 : ((mode == 1) ? g_sc : g_bb);
    int c = blockIdx.x;
    float s = 0.f, s2 = 0.f;
    for (int b = 0; b < 16; b++) {
        const float4* p = (const float4*)(buf + ((size_t)(b * 256 + c)) * HWp);
        for (int i = threadIdx.x; i < 1024; i += 256) {
            float4 v = p[i];
            s  += v.x + v.y + v.z + v.w;
            s2 += v.x * v.x + v.y * v.y + v.z * v.z + v.w * v.w;
        }
    }
    int lane = threadIdx.x & 31, w = threadIdx.x >> 5;
#pragma unroll
    for (int o = 16; o; o >>= 1) {
        s  += __shfl_down_sync(0xffffffffu, s, o);
        s2 += __shfl_down_sync(0xffffffffu, s2, o);
    }
    __shared__ float sm[2][8];
    if (lane == 0) { sm[0][w] = s; sm[1][w] = s2; }
    __syncthreads();
    if (threadIdx.x == 0) {
        float S = 0.f, S2 = 0.f;
#pragma unroll
        for (int j = 0; j < 8; j++) { S += sm[0][j]; S2 += sm[1][j]; }
        const float inv_n = 1.0f / (16.0f * 4096.0f);
        float mean = S * inv_n;
        float var  = S2 * inv_n - mean * mean;
        float sc = g[c] * rsqrtf(var + 1e-5f);
        float bi = be[c] - mean * sc;
        if (mode == 0)      { g_scale1[c] = sc; g_bias1[c] = bi; }
        else if (mode == 1) { g_scaleS[c] = sc; g_biasS[c] = bi; }
        else                { g_scale2[c] = sc; g_bias2[c] = bi; }
    }
}

// ---------------------------------------------------------------------------
// Kernel 6: out = silu( bn2(bb) + bns(sc) ), elementwise float4.
// ---------------------------------------------------------------------------
__global__ void k_final(float* __restrict__ out) {
    int i4 = blockIdx.x * 256 + threadIdx.x;
    if (i4 >= NTOT / 4) return;
    int idx = i4 * 4;
    int c = (idx >> 12) & 255;
    float s2 = g_scale2[c], b2 = g_bias2[c];
    float ss = g_scaleS[c], bs = g_biasS[c];
    float4 vb = ((const float4*)g_bb)[i4];
    float4 vs = ((const float4*)g_sc)[i4];
    float4 r;
    r.x = silu_f(fmaf(s2, vb.x, b2) + fmaf(ss, vs.x, bs));
    r.y = silu_f(fmaf(s2, vb.y, b2) + fmaf(ss, vs.y, bs));
    r.z = silu_f(fmaf(s2, vb.z, b2) + fmaf(ss, vs.z, bs));
    r.w = silu_f(fmaf(s2, vb.w, b2) + fmaf(ss, vs.w, bs));
    ((float4*)out)[i4] = r;
}

// ---------------------------------------------------------------------------
extern "C" void kernel_launch(void* const* d_in, const int* in_sizes, int n_in,
                              void* d_out, int out_size) {
    const float* x     = (const float*)d_in[0];
    const float* dce   = (const float*)d_in[1];
    const float* w_dce = (const float*)d_in[2];
    const float* b_dce = (const float*)d_in[3];
    const float* w_ch  = (const float*)d_in[4];
    const float* w_sh  = (const float*)d_in[5];
    const float* b_sh  = (const float*)d_in[6];
    const float* w_ex  = (const float*)d_in[7];
    const float* b_ex  = (const float*)d_in[8];
    const float* w1    = (const float*)d_in[9];
    const float* g1    = (const float*)d_in[10];
    const float* be1   = (const float*)d_in[11];
    const float* w2    = (const float*)d_in[12];
    const float* g2    = (const float*)d_in[13];
    const float* be2   = (const float*)d_in[14];
    const float* wsc   = (const float*)d_in[15];
    const float* gs    = (const float*)d_in[16];
    const float* bes   = (const float*)d_in[17];

    static bool attr_done = false;
    if (!attr_done) {
        cudaFuncSetAttribute(k_tmma<0>, cudaFuncAttributeMaxDynamicSharedMemorySize, SMEM_DYN);
        cudaFuncSetAttribute(k_tmma<1>, cudaFuncAttributeMaxDynamicSharedMemorySize, SMEM_DYN);
        cudaFuncSetAttribute(k_tmma<2>, cudaFuncAttributeMaxDynamicSharedMemorySize, SMEM_DYN);
        attr_done = true;
    }

    dim3 gconv(32, 2, 16);

    k_wt<<<2304, 256>>>(w1);
    k_wround<<<256, 256>>>(wsc, w2);
    k_spatial<<<4096, 256>>>(x, w_ch);
    k_gate<<<16, 256>>>(dce, w_dce, b_dce, w_sh, b_sh, w_ex, b_ex);
    k_xm<<<16384, 256>>>(x);                    // g_xm = rna(x*mod)
    k_tmma<0><<<gconv, 256, SMEM_DYN>>>();      // conv1 -> g_y1
    k_tmma<1><<<gconv, 256, SMEM_DYN>>>();      // shortcut -> g_sc
    k_stats<<<256, 256>>>(0, g1, be1);          // bn1 params
    k_stats<<<256, 256>>>(1, gs, bes);          // bns params
    k_a1<<<16384, 256>>>();                     // g_a1 = rna(silu(bn1(y1)))
    k_tmma<2><<<gconv, 256, SMEM_DYN>>>();      // conv2 -> g_bb
    k_stats<<<256, 256>>>(2, g2, be2);          // bn2 params
    k_final<<<16384, 256>>>((float*)d_out);
}

// round 11
// speedup vs baseline: 3.4677x; 1.0619x over previous
#include <cuda_runtime.h>
#include <math.h>
#include <stdint.h>

#define BB   16
#define CC   256
#define HWp  4096
#define NTOT (16*256*4096)

// ---------------- device-global scratch (no allocations allowed) ----------------
__device__ float g_spatial[BB*CC];
__device__ float g_pooled[BB*128];
__device__ float g_mvec[BB*CC];
__device__ float g_hvec[BB*128];
__device__ float g_mod[BB*CC];
__device__ float g_w1t[9*256*256];   // conv1 weights transposed+rounded: [tap][co][ci]
__device__ float g_wscr[256*256];    // rounded shortcut weights [co][ci]
__device__ float g_w2r[256*256];     // rounded conv2 weights   [co][ci]
__device__ float g_xm[NTOT];         // rna(x * mod)
__device__ float g_y1[NTOT];
__device__ float g_sc[NTOT];
__device__ float g_bb[NTOT];
__device__ float g_ps[3][512*256];   // per-(b,pxtile) channel partial sums
__device__ float g_pq[3][512*256];   // per-(b,pxtile) channel partial sumsq
__device__ float g_scale1[CC], g_bias1[CC];
__device__ float g_scaleS[CC], g_biasS[CC];
__device__ float g_scale2[CC], g_bias2[CC];

__device__ __forceinline__ float silu_f(float z) {
    return z / (1.0f + __expf(-z));
}
__device__ __forceinline__ float tf32r(float x) {
    unsigned u;
    asm("cvt.rna.tf32.f32 %0, %1;" : "=r"(u) : "f"(x));
    return __uint_as_float(u);
}
__device__ __forceinline__ uint32_t smem_u32(const void* p) {
    uint32_t a;
    asm("{ .reg .u64 t; cvta.to.shared.u64 t, %1; cvt.u32.u64 %0, t; }" : "=r"(a) : "l"(p));
    return a;
}

#define CP16(dst, src) \
    asm volatile("cp.async.ca.shared.global [%0], [%1], 16;" :: "r"(dst), "l"(src) : "memory")
#define CP4Z(dst, src, sz) \
    asm volatile("cp.async.ca.shared.global [%0], [%1], 4, %2;" :: "r"(dst), "l"(src), "r"(sz) : "memory")
#define CP_COMMIT() asm volatile("cp.async.commit_group;" ::: "memory")
#define CP_WAIT(n)  asm volatile("cp.async.wait_group %0;" :: "n"(n) : "memory")

#define MMA8(d, a, b0, b1) \
    asm volatile("mma.sync.aligned.m16n8k8.row.col.f32.tf32.tf32.f32 " \
                 "{%0,%1,%2,%3}, {%4,%5,%6,%7}, {%8,%9}, {%0,%1,%2,%3};" \
                 : "+f"((d)[0]), "+f"((d)[1]), "+f"((d)[2]), "+f"((d)[3]) \
                 : "r"((a)[0]), "r"((a)[1]), "r"((a)[2]), "r"((a)[3]), "r"(b0), "r"(b1))

// ---------------------------------------------------------------------------
// Kernel 0a: conv1 weight transpose+round w1[co][ci][tap] -> g_w1t[tap][co][ci]
// ---------------------------------------------------------------------------
__global__ void k_wt(const float* __restrict__ w1) {
    int i = blockIdx.x * 256 + threadIdx.x;
    if (i >= 9 * 256 * 256) return;
    int tap = i % 9;
    int rest = i / 9;
    int ci = rest & 255;
    int co = rest >> 8;
    g_w1t[((tap << 8) + co) * 256 + ci] = tf32r(w1[i]);
}

// Kernel 0b: round 1x1 weights
__global__ void k_wround(const float* __restrict__ wsc, const float* __restrict__ w2) {
    int i = blockIdx.x * 256 + threadIdx.x;
    if (i >= 256 * 256) return;
    g_wscr[i] = tf32r(wsc[i]);
    g_w2r[i]  = tf32r(w2[i]);
}

// ---------------------------------------------------------------------------
// Kernel 1: spatial_proj via inclusion-exclusion (exact)
// ---------------------------------------------------------------------------
__global__ void k_spatial(const float* __restrict__ x, const float* __restrict__ w_ch) {
    int bc = blockIdx.x;
    const float* p = x + (size_t)bc * HWp;
    float T = 0.f, R0 = 0.f, R1 = 0.f, C0 = 0.f, C1 = 0.f;
    for (int k = threadIdx.x; k < HWp; k += 256) {
        float v = p[k];
        int i = k >> 6, j = k & 63;
        T += v;
        R0 += (i == 0)  ? v : 0.f;
        R1 += (i == 63) ? v : 0.f;
        C0 += (j == 0)  ? v : 0.f;
        C1 += (j == 63) ? v : 0.f;
    }
    __shared__ float sm[5][8];
    float vals[5] = {T, R0, R1, C0, C1};
    int lane = threadIdx.x & 31, w = threadIdx.x >> 5;
#pragma unroll
    for (int i = 0; i < 5; i++) {
        float v = vals[i];
#pragma unroll
        for (int o = 16; o; o >>= 1) v += __shfl_down_sync(0xffffffffu, v, o);
        if (lane == 0) sm[i][w] = v;
    }
    __syncthreads();
    if (threadIdx.x == 0) {
        float r[5];
#pragma unroll
        for (int i = 0; i < 5; i++) {
            float s = 0.f;
#pragma unroll
            for (int j = 0; j < 8; j++) s += sm[i][j];
            r[i] = s;
        }
        float Tt = r[0], Ra = r[1], Rb = r[2], Ca = r[3], Cb = r[4];
        float x00 = p[0], x0W = p[63], xH0 = p[63 * 64], xHW = p[4095];
        float S[9] = {
            Tt - Rb - Cb + xHW,  Tt - Rb,  Tt - Rb - Ca + xH0,
            Tt - Cb,             Tt,       Tt - Ca,
            Tt - Ra - Cb + x0W,  Tt - Ra,  Tt - Ra - Ca + x00
        };
        int c = bc & 255;
        const float* wc = w_ch + c * 9;
        float s = 0.f;
#pragma unroll
        for (int k = 0; k < 9; k++) s += wc[k] * S[k];
        g_spatial[bc] = s * (1.0f / 4096.0f);
    }
}

// ---------------------------------------------------------------------------
// Gate MLP, parallelized: pool -> L1 (dot128) -> L2 (dot256,relu) -> L3 (dot128,sigmoid)
// Warp-per-output with shfl reduction.
// ---------------------------------------------------------------------------
__global__ void k_pool(const float* __restrict__ dce) {
    int b = blockIdx.x, t = threadIdx.x;   // 128 threads
    const float* dp = dce + b * 100 * 128 + t;
    float s = 0.f;
#pragma unroll 4
    for (int l = 0; l < 100; l++) s += dp[l * 128];
    g_pooled[b * 128 + t] = s * (1.0f / 100.0f);
}

__global__ void k_gate1(const float* __restrict__ w_dce, const float* __restrict__ b_dce) {
    // grid (8, 16), 128 thr: block covers 32 outputs of (b=by), warp -> 8 outputs
    int b = blockIdx.y;
    int l = threadIdx.x & 31, w = threadIdx.x >> 5;
    __shared__ float ps[128];
    ps[threadIdx.x] = g_pooled[b * 128 + threadIdx.x];
    __syncthreads();
    float p0 = ps[l], p1 = ps[l + 32], p2 = ps[l + 64], p3 = ps[l + 96];
#pragma unroll
    for (int o = 0; o < 8; o++) {
        int co = blockIdx.x * 32 + w * 8 + o;
        const float* wr = w_dce + co * 128;
        float s = wr[l] * p0 + wr[l + 32] * p1 + wr[l + 64] * p2 + wr[l + 96] * p3;
#pragma unroll
        for (int of = 16; of; of >>= 1) s += __shfl_down_sync(0xffffffffu, s, of);
        if (l == 0) g_mvec[b * 256 + co] = (s + b_dce[co]) * g_spatial[b * 256 + co];
    }
}

__global__ void k_gate2(const float* __restrict__ w_sh, const float* __restrict__ b_sh) {
    // grid (4, 16), 128 thr: 32 outputs/block, dot-256
    int b = blockIdx.y;
    int l = threadIdx.x & 31, w = threadIdx.x >> 5;
    __shared__ float ms[256];
    ms[threadIdx.x] = g_mvec[b * 256 + threadIdx.x];
    ms[threadIdx.x + 128] = g_mvec[b * 256 + threadIdx.x + 128];
    __syncthreads();
    float m[8];
#pragma unroll
    for (int q = 0; q < 8; q++) m[q] = ms[l + q * 32];
#pragma unroll
    for (int o = 0; o < 8; o++) {
        int co = blockIdx.x * 32 + w * 8 + o;
        const float* wr = w_sh + co * 256;
        float s = 0.f;
#pragma unroll
        for (int q = 0; q < 8; q++) s += wr[l + q * 32] * m[q];
#pragma unroll
        for (int of = 16; of; of >>= 1) s += __shfl_down_sync(0xffffffffu, s, of);
        if (l == 0) g_hvec[b * 128 + co] = fmaxf(s + b_sh[co], 0.f);
    }
}

__global__ void k_gate3(const float* __restrict__ w_ex, const float* __restrict__ b_ex) {
    // grid (8, 16), 128 thr: 32 outputs/block, dot-128
    int b = blockIdx.y;
    int l = threadIdx.x & 31, w = threadIdx.x >> 5;
    __shared__ float hs[128];
    hs[threadIdx.x] = g_hvec[b * 128 + threadIdx.x];
    __syncthreads();
    float h0 = hs[l], h1 = hs[l + 32], h2 = hs[l + 64], h3 = hs[l + 96];
#pragma unroll
    for (int o = 0; o < 8; o++) {
        int co = blockIdx.x * 32 + w * 8 + o;
        const float* wr = w_ex + co * 128;
        float s = wr[l] * h0 + wr[l + 32] * h1 + wr[l + 64] * h2 + wr[l + 96] * h3;
#pragma unroll
        for (int of = 16; of; of >>= 1) s += __shfl_down_sync(0xffffffffu, s, of);
        if (l == 0) g_mod[b * 256 + co] = 1.0f / (1.0f + expf(-(s + b_ex[co])));
    }
}

// ---------------------------------------------------------------------------
// Kernel 3a: g_xm = rna(x * mod)   (float4 elementwise)
// ---------------------------------------------------------------------------
__global__ void k_xm(const float* __restrict__ x) {
    int i4 = blockIdx.x * 256 + threadIdx.x;
    if (i4 >= NTOT / 4) return;
    int idx = i4 * 4;
    int c = (idx >> 12) & 255;
    int b = idx >> 20;
    float m = g_mod[b * 256 + c];
    float4 v = ((const float4*)x)[i4];
    v.x = tf32r(v.x * m); v.y = tf32r(v.y * m);
    v.z = tf32r(v.z * m); v.w = tf32r(v.w * m);
    ((float4*)g_xm)[i4] = v;
}

// ---------------------------------------------------------------------------
// Tensor kernel: tf32 warp-MMA implicit GEMM with fused BN-stat partials.
//   D[px(128)][co(128)] = sum_k A[px][k] * W[co][k]
//   KIND 0: conv1  (A=g_xm, im2col 9 taps, W=g_w1t, out=g_y1)
//   KIND 1: shortcut 1x1 (A=g_xm, W=g_wscr, out=g_sc)
//   KIND 2: conv2 1x1    (A=silu(bn1(g_y1)) fused in staging, W=g_w2r, out=g_bb)
// grid = (32 px tiles, 2 co tiles, 16 batch), 256 threads (8 warps 4m x 2n).
// ---------------------------------------------------------------------------
#define PA 136
#define PB 36
#define ABUF (32*PA)
#define BBUF2 (128*PB)
#define BUFF (ABUF + BBUF2)
#define SMEM_DYN (2 * BUFF * 4)

template <int KIND>
__global__ __launch_bounds__(256, 2) void k_tmma(void) {
    extern __shared__ float smf[];
    const uint32_t sbase = smem_u32(smf);
    const int tid = threadIdx.x;
    const int b = blockIdx.z;
    const int cob = blockIdx.y * 128;
    const int pxb = blockIdx.x * 128;

    const float* in   = (KIND == 2) ? g_y1 : g_xm;
    const float* wsrc = (KIND == 0) ? g_w1t : ((KIND == 1) ? g_wscr : g_w2r);
    float* out        = (KIND == 0) ? g_y1 : ((KIND == 1) ? g_sc : g_bb);
    const int NTAPS = (KIND == 0) ? 9 : 1;
    const int NCH = NTAPS * 8;

    const int l = tid & 31, wid = tid >> 5;
    const int warp_m = wid & 3, warp_n = wid >> 2;
    const int g = l >> 2, tg = l & 3;

    float d[2][8][4];
#pragma unroll
    for (int mt = 0; mt < 2; mt++)
#pragma unroll
        for (int nt = 0; nt < 8; nt++)
#pragma unroll
            for (int j = 0; j < 4; j++) d[mt][nt][j] = 0.f;

    // ---- staging ----
    auto stage = [&](int cc, int s) {
        uint32_t aB = sbase + (uint32_t)(s * BUFF) * 4u;
        uint32_t bB = aB + ABUF * 4u;
        int tap = (NTAPS == 9) ? (cc >> 3) : 0;
        int kb  = ((NTAPS == 9) ? (cc & 7) : cc) * 32;
        if (KIND == 0) {
            int dy = tap / 3 - 1, dx = tap % 3 - 1;
            const float* basep = in + ((size_t)(b * 256 + kb) << 12) + dy * 64 + dx;
#pragma unroll
            for (int it = 0; it < 16; it++) {
                int item = it * 256 + tid;
                int k = item >> 7, px = item & 127;
                int pxg = pxb + px;
                int rr = (pxg >> 6) + dy, cc2 = (pxg & 63) + dx;
                unsigned ok = (((unsigned)rr < 64u) && ((unsigned)cc2 < 64u)) ? 4u : 0u;
                CP4Z(aB + (uint32_t)(k * PA + px) * 4u, basep + ((size_t)k << 12) + pxg, ok);
            }
        } else if (KIND == 1) {
            const float* basep = in + ((size_t)(b * 256 + kb) << 12) + pxb;
#pragma unroll
            for (int it = 0; it < 4; it++) {
                int item = it * 256 + tid;
                int k = item >> 5, q = item & 31;
                CP16(aB + (uint32_t)(k * PA + q * 4) * 4u, basep + ((size_t)k << 12) + q * 4);
            }
        } else {
            // KIND 2: fused silu(bn1(y1)) + tf32 round via LDG->STS
            const float* basep = in + ((size_t)(b * 256 + kb) << 12) + pxb;
            float* aF = smf + s * BUFF;
#pragma unroll
            for (int it = 0; it < 4; it++) {
                int item = it * 256 + tid;
                int k = item >> 5, q = item & 31;
                float4 v = *(const float4*)(basep + ((size_t)k << 12) + q * 4);
                float s1 = g_scale1[kb + k], t1 = g_bias1[kb + k];
                v.x = tf32r(silu_f(fmaf(s1, v.x, t1)));
                v.y = tf32r(silu_f(fmaf(s1, v.y, t1)));
                v.z = tf32r(silu_f(fmaf(s1, v.z, t1)));
                v.w = tf32r(silu_f(fmaf(s1, v.w, t1)));
                *(float4*)(aF + k * PA + q * 4) = v;
            }
        }
        {
            const float* wp = wsrc + ((size_t)(((NTAPS == 9) ? tap * 256 : 0) + cob)) * 256 + kb;
#pragma unroll
            for (int it = 0; it < 4; it++) {
                int item = it * 256 + tid;
                int col = item >> 3, kq = item & 7;
                CP16(bB + (uint32_t)(col * PB + kq * 4) * 4u, wp + (size_t)col * 256 + kq * 4);
            }
        }
    };

    stage(0, 0);
    CP_COMMIT();

    for (int ch = 0; ch < NCH; ch++) {
        if (ch + 1 < NCH) {
            stage(ch + 1, (ch + 1) & 1);
            CP_COMMIT();
            CP_WAIT(1);
        } else {
            CP_WAIT(0);
        }
        __syncthreads();   // chunk ch visible to all warps

        const float* As = smf + (ch & 1) * BUFF;
        const float* Bs = As + ABUF;
#pragma unroll
        for (int kt = 0; kt < 4; kt++) {
            int kk = kt * 8 + tg;
            uint32_t a[2][4];
#pragma unroll
            for (int mt = 0; mt < 2; mt++) {
                int m0 = warp_m * 32 + mt * 16 + g;
                a[mt][0] = __float_as_uint(As[kk * PA + m0]);
                a[mt][1] = __float_as_uint(As[kk * PA + m0 + 8]);
                a[mt][2] = __float_as_uint(As[(kk + 4) * PA + m0]);
                a[mt][3] = __float_as_uint(As[(kk + 4) * PA + m0 + 8]);
            }
#pragma unroll
            for (int nt = 0; nt < 8; nt++) {
                int n0 = warp_n * 64 + nt * 8 + g;
                uint32_t b0 = __float_as_uint(Bs[n0 * PB + kk]);
                uint32_t b1 = __float_as_uint(Bs[n0 * PB + kk + 4]);
                MMA8(d[0][nt], a[0], b0, b1);
                MMA8(d[1][nt], a[1], b0, b1);
            }
        }
        __syncthreads();   // all warps done with buffer before next overwrite
    }

    // ---- epilogue: stores + per-channel (sum, sumsq) partials ----
#pragma unroll
    for (int mt = 0; mt < 2; mt++) {
        int px = pxb + warp_m * 32 + mt * 16 + g;
#pragma unroll
        for (int nt = 0; nt < 8; nt++) {
            int co = cob + warp_n * 64 + nt * 8 + tg * 2;
            float* o = out + (((size_t)(b * 256 + co)) << 12) + px;
            o[0]    = d[mt][nt][0];
            o[4096] = d[mt][nt][1];
            o[8]    = d[mt][nt][2];
            o[4104] = d[mt][nt][3];
        }
    }

    __shared__ float eps[4][128], epq[4][128];
#pragma unroll
    for (int nt = 0; nt < 8; nt++) {
        float s0 = d[0][nt][0] + d[0][nt][2] + d[1][nt][0] + d[1][nt][2];
        float s1 = d[0][nt][1] + d[0][nt][3] + d[1][nt][1] + d[1][nt][3];
        float q0 = d[0][nt][0] * d[0][nt][0] + d[0][nt][2] * d[0][nt][2]
                 + d[1][nt][0] * d[1][nt][0] + d[1][nt][2] * d[1][nt][2];
        float q1 = d[0][nt][1] * d[0][nt][1] + d[0][nt][3] * d[0][nt][3]
                 + d[1][nt][1] * d[1][nt][1] + d[1][nt][3] * d[1][nt][3];
#pragma unroll
        for (int of = 4; of <= 16; of <<= 1) {
            s0 += __shfl_xor_sync(0xffffffffu, s0, of);
            s1 += __shfl_xor_sync(0xffffffffu, s1, of);
            q0 += __shfl_xor_sync(0xffffffffu, q0, of);
            q1 += __shfl_xor_sync(0xffffffffu, q1, of);
        }
        if (l < 4) {
            int cl = warp_n * 64 + nt * 8 + l * 2;
            eps[warp_m][cl] = s0; eps[warp_m][cl + 1] = s1;
            epq[warp_m][cl] = q0; epq[warp_m][cl + 1] = q1;
        }
    }
    __syncthreads();
    if (tid < 128) {
        float S = eps[0][tid] + eps[1][tid] + eps[2][tid] + eps[3][tid];
        float Q = epq[0][tid] + epq[1][tid] + epq[2][tid] + epq[3][tid];
        int slot = b * 32 + blockIdx.x;
        g_ps[KIND][slot * 256 + cob + tid] = S;
        g_pq[KIND][slot * 256 + cob + tid] = Q;
    }
}

// ---------------------------------------------------------------------------
// Kernel 5: finalize BN stats from partials. grid = 256 channels, 128 threads.
// ---------------------------------------------------------------------------
__global__ void k_fin(int mode, const float* __restrict__ g, const float* __restrict__ be) {
    int c = blockIdx.x, t = threadIdx.x;
    const float* PS = g_ps[mode];
    const float* PQ = g_pq[mode];
    float s = 0.f, q = 0.f;
    for (int i = t; i < 512; i += 128) { s += PS[i * 256 + c]; q += PQ[i * 256 + c]; }
    __shared__ float ss[128], sq[128];
    ss[t] = s; sq[t] = q;
    __syncthreads();
    for (int of = 64; of; of >>= 1) {
        if (t < of) { ss[t] += ss[t + of]; sq[t] += sq[t + of]; }
        __syncthreads();
    }
    if (t == 0) {
        const float inv_n = 1.0f / (16.0f * 4096.0f);
        float mean = ss[0] * inv_n;
        float var  = sq[0] * inv_n - mean * mean;
        float sc = g[c] * rsqrtf(var + 1e-5f);
        float bi = be[c] - mean * sc;
        if (mode == 0)      { g_scale1[c] = sc; g_bias1[c] = bi; }
        else if (mode == 1) { g_scaleS[c] = sc; g_biasS[c] = bi; }
        else                { g_scale2[c] = sc; g_bias2[c] = bi; }
    }
}

// ---------------------------------------------------------------------------
// Kernel 6: out = silu( bn2(bb) + bns(sc) ), elementwise float4.
// ---------------------------------------------------------------------------
__global__ void k_final(float* __restrict__ out) {
    int i4 = blockIdx.x * 256 + threadIdx.x;
    if (i4 >= NTOT / 4) return;
    int idx = i4 * 4;
    int c = (idx >> 12) & 255;
    float s2 = g_scale2[c], b2 = g_bias2[c];
    float ss = g_scaleS[c], bs = g_biasS[c];
    float4 vb = ((const float4*)g_bb)[i4];
    float4 vs = ((const float4*)g_sc)[i4];
    float4 r;
    r.x = silu_f(fmaf(s2, vb.x, b2) + fmaf(ss, vs.x, bs));
    r.y = silu_f(fmaf(s2, vb.y, b2) + fmaf(ss, vs.y, bs));
    r.z = silu_f(fmaf(s2, vb.z, b2) + fmaf(ss, vs.z, bs));
    r.w = silu_f(fmaf(s2, vb.w, b2) + fmaf(ss, vs.w, bs));
    ((float4*)out)[i4] = r;
}

// ---------------------------------------------------------------------------
extern "C" void kernel_launch(void* const* d_in, const int* in_sizes, int n_in,
                              void* d_out, int out_size) {
    const float* x     = (const float*)d_in[0];
    const float* dce   = (const float*)d_in[1];
    const float* w_dce = (const float*)d_in[2];
    const float* b_dce = (const float*)d_in[3];
    const float* w_ch  = (const float*)d_in[4];
    const float* w_sh  = (const float*)d_in[5];
    const float* b_sh  = (const float*)d_in[6];
    const float* w_ex  = (const float*)d_in[7];
    const float* b_ex  = (const float*)d_in[8];
    const float* w1    = (const float*)d_in[9];
    const float* g1    = (const float*)d_in[10];
    const float* be1   = (const float*)d_in[11];
    const float* w2    = (const float*)d_in[12];
    const float* g2    = (const float*)d_in[13];
    const float* be2   = (const float*)d_in[14];
    const float* wsc   = (const float*)d_in[15];
    const float* gs    = (const float*)d_in[16];
    const float* bes   = (const float*)d_in[17];

    cudaFuncSetAttribute(k_tmma<0>, cudaFuncAttributeMaxDynamicSharedMemorySize, SMEM_DYN);
    cudaFuncSetAttribute(k_tmma<1>, cudaFuncAttributeMaxDynamicSharedMemorySize, SMEM_DYN);
    cudaFuncSetAttribute(k_tmma<2>, cudaFuncAttributeMaxDynamicSharedMemorySize, SMEM_DYN);

    dim3 gconv(32, 2, 16);

    k_wt<<<2304, 256>>>(w1);
    k_wround<<<256, 256>>>(wsc, w2);
    k_spatial<<<4096, 256>>>(x, w_ch);
    k_pool<<<16, 128>>>(dce);
    k_gate1<<<dim3(8, 16), 128>>>(w_dce, b_dce);
    k_gate2<<<dim3(4, 16), 128>>>(w_sh, b_sh);
    k_gate3<<<dim3(8, 16), 128>>>(w_ex, b_ex);
    k_xm<<<16384, 256>>>(x);                    // g_xm = rna(x*mod)
    k_tmma<0><<<gconv, 256, SMEM_DYN>>>();      // conv1 -> g_y1 (+bn1 partials)
    k_tmma<1><<<gconv, 256, SMEM_DYN>>>();      // shortcut -> g_sc (+bns partials)
    k_fin<<<256, 128>>>(0, g1, be1);            // bn1 scale/bias
    k_fin<<<256, 128>>>(1, gs, bes);            // bns scale/bias
    k_tmma<2><<<gconv, 256, SMEM_DYN>>>();      // conv2 (fused silu(bn1)) -> g_bb
    k_fin<<<256, 128>>>(2, g2, be2);            // bn2 scale/bias
    k_final<<<16384, 256>>>((float*)d_out);
}

// round 13
// speedup vs baseline: 3.6432x; 1.0506x over previous
#include <cuda_runtime.h>
#include <math.h>
#include <stdint.h>

#define BB   16
#define CC   256
#define HWp  4096
#define NTOT (16*256*4096)

// ---------------- device-global scratch (no allocations allowed) ----------------
__device__ float g_spatial[BB*CC];
__device__ float g_pooled[BB*128];
__device__ float g_mvec[BB*CC];
__device__ float g_hvec[BB*128];
__device__ float g_mod[BB*CC];
__device__ float g_w1t[9*256*256];   // conv1 weights transposed+rounded: [tap][co][ci]
__device__ float g_wscr[256*256];    // rounded shortcut weights [co][ci]
__device__ float g_w2r[256*256];     // rounded conv2 weights   [co][ci]
__device__ float g_xm[NTOT];         // rna(x * mod)
__device__ float g_y1[NTOT];
__device__ float g_sc[NTOT];
__device__ float g_bb[NTOT];
__device__ float g_ps[3][512*256];   // per-(b,pxtile) channel partial sums
__device__ float g_pq[3][512*256];   // per-(b,pxtile) channel partial sumsq
__device__ float g_scale1[CC], g_bias1[CC];
__device__ float g_scaleS[CC], g_biasS[CC];
__device__ float g_scale2[CC], g_bias2[CC];

__device__ __forceinline__ float silu_f(float z) {
    return z / (1.0f + __expf(-z));
}
__device__ __forceinline__ float tf32r(float x) {
    unsigned u;
    asm("cvt.rna.tf32.f32 %0, %1;" : "=r"(u) : "f"(x));
    return __uint_as_float(u);
}
__device__ __forceinline__ uint32_t smem_u32(const void* p) {
    uint32_t a;
    asm("{ .reg .u64 t; cvta.to.shared.u64 t, %1; cvt.u32.u64 %0, t; }" : "=r"(a) : "l"(p));
    return a;
}

#define CP16(dst, src) \
    asm volatile("cp.async.ca.shared.global [%0], [%1], 16;" :: "r"(dst), "l"(src) : "memory")
#define CP16Z(dst, src, sz) \
    asm volatile("cp.async.ca.shared.global [%0], [%1], 16, %2;" :: "r"(dst), "l"(src), "r"(sz) : "memory")
#define CP_COMMIT() asm volatile("cp.async.commit_group;" ::: "memory")
#define CP_WAIT(n)  asm volatile("cp.async.wait_group %0;" :: "n"(n) : "memory")

#define MMA8(d, a, b0, b1) \
    asm volatile("mma.sync.aligned.m16n8k8.row.col.f32.tf32.tf32.f32 " \
                 "{%0,%1,%2,%3}, {%4,%5,%6,%7}, {%8,%9}, {%0,%1,%2,%3};" \
                 : "+f"((d)[0]), "+f"((d)[1]), "+f"((d)[2]), "+f"((d)[3]) \
                 : "r"((a)[0]), "r"((a)[1]), "r"((a)[2]), "r"((a)[3]), "r"(b0), "r"(b1))

// ---------------------------------------------------------------------------
// Kernel 0a: conv1 weight transpose+round w1[co][ci][tap] -> g_w1t[tap][co][ci]
// ---------------------------------------------------------------------------
__global__ void k_wt(const float* __restrict__ w1) {
    int i = blockIdx.x * 256 + threadIdx.x;
    if (i >= 9 * 256 * 256) return;
    int tap = i % 9;
    int rest = i / 9;
    int ci = rest & 255;
    int co = rest >> 8;
    g_w1t[((tap << 8) + co) * 256 + ci] = tf32r(w1[i]);
}

// Kernel 0b: round 1x1 weights
__global__ void k_wround(const float* __restrict__ wsc, const float* __restrict__ w2) {
    int i = blockIdx.x * 256 + threadIdx.x;
    if (i >= 256 * 256) return;
    g_wscr[i] = tf32r(wsc[i]);
    g_w2r[i]  = tf32r(w2[i]);
}

// ---------------------------------------------------------------------------
// Kernel 1: spatial_proj via inclusion-exclusion (exact)
// ---------------------------------------------------------------------------
__global__ void k_spatial(const float* __restrict__ x, const float* __restrict__ w_ch) {
    int bc = blockIdx.x;
    const float* p = x + (size_t)bc * HWp;
    float T = 0.f, R0 = 0.f, R1 = 0.f, C0 = 0.f, C1 = 0.f;
    for (int k = threadIdx.x; k < HWp; k += 256) {
        float v = p[k];
        int i = k >> 6, j = k & 63;
        T += v;
        R0 += (i == 0)  ? v : 0.f;
        R1 += (i == 63) ? v : 0.f;
        C0 += (j == 0)  ? v : 0.f;
        C1 += (j == 63) ? v : 0.f;
    }
    __shared__ float sm[5][8];
    float vals[5] = {T, R0, R1, C0, C1};
    int lane = threadIdx.x & 31, w = threadIdx.x >> 5;
#pragma unroll
    for (int i = 0; i < 5; i++) {
        float v = vals[i];
#pragma unroll
        for (int o = 16; o; o >>= 1) v += __shfl_down_sync(0xffffffffu, v, o);
        if (lane == 0) sm[i][w] = v;
    }
    __syncthreads();
    if (threadIdx.x == 0) {
        float r[5];
#pragma unroll
        for (int i = 0; i < 5; i++) {
            float s = 0.f;
#pragma unroll
            for (int j = 0; j < 8; j++) s += sm[i][j];
            r[i] = s;
        }
        float Tt = r[0], Ra = r[1], Rb = r[2], Ca = r[3], Cb = r[4];
        float x00 = p[0], x0W = p[63], xH0 = p[63 * 64], xHW = p[4095];
        float S[9] = {
            Tt - Rb - Cb + xHW,  Tt - Rb,  Tt - Rb - Ca + xH0,
            Tt - Cb,             Tt,       Tt - Ca,
            Tt - Ra - Cb + x0W,  Tt - Ra,  Tt - Ra - Ca + x00
        };
        int c = bc & 255;
        const float* wc = w_ch + c * 9;
        float s = 0.f;
#pragma unroll
        for (int k = 0; k < 9; k++) s += wc[k] * S[k];
        g_spatial[bc] = s * (1.0f / 4096.0f);
    }
}

// ---------------------------------------------------------------------------
// Gate MLP, parallelized.
// ---------------------------------------------------------------------------
__global__ void k_pool(const float* __restrict__ dce) {
    int b = blockIdx.x, t = threadIdx.x;   // 1024 threads
    int col = t & 127, part = t >> 7;      // 8 partials per column
    const float* dp = dce + b * 100 * 128 + col;
    float s = 0.f;
    for (int l = part; l < 100; l += 8) s += dp[l * 128];
    __shared__ float sm[8][128];
    sm[part][col] = s;
    __syncthreads();
    if (t < 128) {
        float v = 0.f;
#pragma unroll
        for (int p = 0; p < 8; p++) v += sm[p][t];
        g_pooled[b * 128 + t] = v * (1.0f / 100.0f);
    }
}

__global__ void k_gate1(const float* __restrict__ w_dce, const float* __restrict__ b_dce) {
    int b = blockIdx.y;
    int l = threadIdx.x & 31, w = threadIdx.x >> 5;
    __shared__ float ps[128];
    ps[threadIdx.x] = g_pooled[b * 128 + threadIdx.x];
    __syncthreads();
    float p0 = ps[l], p1 = ps[l + 32], p2 = ps[l + 64], p3 = ps[l + 96];
#pragma unroll
    for (int o = 0; o < 8; o++) {
        int co = blockIdx.x * 32 + w * 8 + o;
        const float* wr = w_dce + co * 128;
        float s = wr[l] * p0 + wr[l + 32] * p1 + wr[l + 64] * p2 + wr[l + 96] * p3;
#pragma unroll
        for (int of = 16; of; of >>= 1) s += __shfl_down_sync(0xffffffffu, s, of);
        if (l == 0) g_mvec[b * 256 + co] = (s + b_dce[co]) * g_spatial[b * 256 + co];
    }
}

__global__ void k_gate2(const float* __restrict__ w_sh, const float* __restrict__ b_sh) {
    int b = blockIdx.y;
    int l = threadIdx.x & 31, w = threadIdx.x >> 5;
    __shared__ float ms[256];
    ms[threadIdx.x] = g_mvec[b * 256 + threadIdx.x];
    ms[threadIdx.x + 128] = g_mvec[b * 256 + threadIdx.x + 128];
    __syncthreads();
    float m[8];
#pragma unroll
    for (int q = 0; q < 8; q++) m[q] = ms[l + q * 32];
#pragma unroll
    for (int o = 0; o < 8; o++) {
        int co = blockIdx.x * 32 + w * 8 + o;
        const float* wr = w_sh + co * 256;
        float s = 0.f;
#pragma unroll
        for (int q = 0; q < 8; q++) s += wr[l + q * 32] * m[q];
#pragma unroll
        for (int of = 16; of; of >>= 1) s += __shfl_down_sync(0xffffffffu, s, of);
        if (l == 0) g_hvec[b * 128 + co] = fmaxf(s + b_sh[co], 0.f);
    }
}

__global__ void k_gate3(const float* __restrict__ w_ex, const float* __restrict__ b_ex) {
    int b = blockIdx.y;
    int l = threadIdx.x & 31, w = threadIdx.x >> 5;
    __shared__ float hs[128];
    hs[threadIdx.x] = g_hvec[b * 128 + threadIdx.x];
    __syncthreads();
    float h0 = hs[l], h1 = hs[l + 32], h2 = hs[l + 64], h3 = hs[l + 96];
#pragma unroll
    for (int o = 0; o < 8; o++) {
        int co = blockIdx.x * 32 + w * 8 + o;
        const float* wr = w_ex + co * 128;
        float s = wr[l] * h0 + wr[l + 32] * h1 + wr[l + 64] * h2 + wr[l + 96] * h3;
#pragma unroll
        for (int of = 16; of; of >>= 1) s += __shfl_down_sync(0xffffffffu, s, of);
        if (l == 0) g_mod[b * 256 + co] = 1.0f / (1.0f + expf(-(s + b_ex[co])));
    }
}

// ---------------------------------------------------------------------------
// Kernel 3a: g_xm = rna(x * mod)
// ---------------------------------------------------------------------------
__global__ void k_xm(const float* __restrict__ x) {
    int i4 = blockIdx.x * 256 + threadIdx.x;
    if (i4 >= NTOT / 4) return;
    int idx = i4 * 4;
    int c = (idx >> 12) & 255;
    int b = idx >> 20;
    float m = g_mod[b * 256 + c];
    float4 v = ((const float4*)x)[i4];
    v.x = tf32r(v.x * m); v.y = tf32r(v.y * m);
    v.z = tf32r(v.z * m); v.w = tf32r(v.w * m);
    ((float4*)g_xm)[i4] = v;
}

// ===========================================================================
// conv1 3x3: halo-panel implicit GEMM.
// CTA: 128 px (= 2 full image rows) x 128 co, batch b.
// Per 16-ci chunk: stage panel P[16k][4 rows][72pad] (rows r0-1..r0+2, cols
// -1..64 at c'=3..68; halo cols constant zero). Then 9 taps read the SAME
// panel with (dy,dx) offsets; B (weights per tap) double-buffered cp.async.
// grid = (32 px tiles, 2 co tiles, 16 batch), 256 threads (8 warps 4m x 2n).
// ===========================================================================
#define ABUFC (16*296)          // floats per A panel buffer
#define BBUFC (128*20)          // floats per B buffer
#define SMEM_C1 ((2*ABUFC + 2*BBUFC) * 4)

__global__ __launch_bounds__(256, 2) void k_conv1(void) {
    extern __shared__ float smf[];
    const uint32_t sbase = smem_u32(smf);
    const int tid = threadIdx.x;
    const int b = blockIdx.z;
    const int cob = blockIdx.y * 128;
    const int pxb = blockIdx.x * 128;
    const int row0 = pxb >> 6;           // first image row of this tile

    const int l = tid & 31, wid = tid >> 5;
    const int warp_m = wid & 3, warp_n = wid >> 2;
    const int g = l >> 2, tg = l & 3;

    const int mrow0 = (warp_m * 32) >> 6;            // mt=0 image-row (0/1)
    const int mrow1 = (warp_m * 32 + 16) >> 6;       // mt=1
    const int mcb0 = (warp_m * 32) & 63;
    const int mcb1 = (warp_m * 32 + 16) & 63;

    float d[2][8][4];
#pragma unroll
    for (int mt = 0; mt < 2; mt++)
#pragma unroll
        for (int nt = 0; nt < 8; nt++)
#pragma unroll
            for (int j = 0; j < 4; j++) d[mt][nt][j] = 0.f;

    // zero the constant halo columns (c'=3 -> gc=-1, c'=68 -> gc=64) of both bufs
    {
        int bf = tid >> 7, rest = tid & 127;
        int k = rest >> 3, r = (rest >> 1) & 3, side = rest & 1;
        smf[bf * ABUFC + k * 296 + r * 72 + (side ? 68 : 3)] = 0.f;
    }

    auto stageA = [&](int cc, int s) {
        int kb = cc * 16;
        uint32_t aB = sbase + (uint32_t)(s * ABUFC) * 4u;
#pragma unroll
        for (int it = 0; it < 4; it++) {
            int item = it * 256 + tid;
            int kr = item >> 4, q = item & 15;
            int k = kr >> 2, r = kr & 3;
            int gr = row0 - 1 + r;
            unsigned ok = ((unsigned)gr < 64u) ? 16u : 0u;
            int grc = (gr < 0) ? 0 : ((gr > 63) ? 63 : gr);
            const float* src = g_xm + ((size_t)(b * 256 + kb + k) << 12) + grc * 64 + q * 4;
            CP16Z(aB + (uint32_t)(k * 296 + r * 72 + 4 + q * 4) * 4u, src, ok);
        }
    };
    auto stageB = [&](int tap, int cc, int s) {
        int kb = cc * 16;
        uint32_t bB = sbase + (uint32_t)(2 * ABUFC + s * BBUFC) * 4u;
        const float* wp = g_w1t + ((size_t)(tap * 256 + cob)) * 256 + kb;
#pragma unroll
        for (int it = 0; it < 2; it++) {
            int item = it * 256 + tid;
            int col = item >> 2, kq = item & 3;
            CP16(bB + (uint32_t)(col * 20 + kq * 4) * 4u, wp + (size_t)col * 256 + kq * 4);
        }
    };

    stageA(0, 0);
    stageB(0, 0, 0);
    CP_COMMIT();

    int iter = 0;
    for (int cc = 0; cc < 16; cc++) {
        const float* As = smf + (cc & 1) * ABUFC;
#pragma unroll 1
        for (int tap = 0; tap < 9; tap++, iter++) {
            int nb = iter & 1;
            if (tap < 8) {
                stageB(tap + 1, cc, nb ^ 1);
                CP_COMMIT(); CP_WAIT(1);
            } else if (cc < 15) {
                stageA(cc + 1, (cc & 1) ^ 1);
                stageB(0, cc + 1, nb ^ 1);
                CP_COMMIT(); CP_WAIT(1);
            } else {
                CP_WAIT(0);
            }
            __syncthreads();

            const float* Bs = smf + 2 * ABUFC + nb * BBUFC;
            int dy = tap / 3 - 1, dx = tap % 3 - 1;
            int rs0 = (mrow0 + dy + 1) * 72;
            int rs1 = (mrow1 + dy + 1) * 72;
            int co0 = 4 + mcb0 + g + dx;
            int co1 = 4 + mcb1 + g + dx;
#pragma unroll
            for (int kt = 0; kt < 2; kt++) {
                int kk = kt * 8 + tg;
                uint32_t a[2][4];
                {
                    const float* p0 = As + kk * 296;
                    const float* p4 = As + (kk + 4) * 296;
                    a[0][0] = __float_as_uint(p0[rs0 + co0]);
                    a[0][1] = __float_as_uint(p0[rs0 + co0 + 8]);
                    a[0][2] = __float_as_uint(p4[rs0 + co0]);
                    a[0][3] = __float_as_uint(p4[rs0 + co0 + 8]);
                    a[1][0] = __float_as_uint(p0[rs1 + co1]);
                    a[1][1] = __float_as_uint(p0[rs1 + co1 + 8]);
                    a[1][2] = __float_as_uint(p4[rs1 + co1]);
                    a[1][3] = __float_as_uint(p4[rs1 + co1 + 8]);
                }
#pragma unroll
                for (int nt = 0; nt < 8; nt++) {
                    int n0 = warp_n * 64 + nt * 8 + g;
                    uint32_t b0 = __float_as_uint(Bs[n0 * 20 + kk]);
                    uint32_t b1 = __float_as_uint(Bs[n0 * 20 + kk + 4]);
                    MMA8(d[0][nt], a[0], b0, b1);
                    MMA8(d[1][nt], a[1], b0, b1);
                }
            }
            __syncthreads();
        }
    }

    // ---- epilogue: stores + per-channel (sum, sumsq) partials ----
#pragma unroll
    for (int mt = 0; mt < 2; mt++) {
        int px = pxb + warp_m * 32 + mt * 16 + g;
#pragma unroll
        for (int nt = 0; nt < 8; nt++) {
            int co = cob + warp_n * 64 + nt * 8 + tg * 2;
            float* o = g_y1 + (((size_t)(b * 256 + co)) << 12) + px;
            o[0]    = d[mt][nt][0];
            o[4096] = d[mt][nt][1];
            o[8]    = d[mt][nt][2];
            o[4104] = d[mt][nt][3];
        }
    }

    __shared__ float eps[4][128], epq[4][128];
#pragma unroll
    for (int nt = 0; nt < 8; nt++) {
        float s0 = d[0][nt][0] + d[0][nt][2] + d[1][nt][0] + d[1][nt][2];
        float s1 = d[0][nt][1] + d[0][nt][3] + d[1][nt][1] + d[1][nt][3];
        float q0 = d[0][nt][0] * d[0][nt][0] + d[0][nt][2] * d[0][nt][2]
                 + d[1][nt][0] * d[1][nt][0] + d[1][nt][2] * d[1][nt][2];
        float q1 = d[0][nt][1] * d[0][nt][1] + d[0][nt][3] * d[0][nt][3]
                 + d[1][nt][1] * d[1][nt][1] + d[1][nt][3] * d[1][nt][3];
#pragma unroll
        for (int of = 4; of <= 16; of <<= 1) {
            s0 += __shfl_xor_sync(0xffffffffu, s0, of);
            s1 += __shfl_xor_sync(0xffffffffu, s1, of);
            q0 += __shfl_xor_sync(0xffffffffu, q0, of);
            q1 += __shfl_xor_sync(0xffffffffu, q1, of);
        }
        if (l < 4) {
            int cl = warp_n * 64 + nt * 8 + l * 2;
            eps[warp_m][cl] = s0; eps[warp_m][cl + 1] = s1;
            epq[warp_m][cl] = q0; epq[warp_m][cl + 1] = q1;
        }
    }
    __syncthreads();
    if (tid < 128) {
        float S = eps[0][tid] + eps[1][tid] + eps[2][tid] + eps[3][tid];
        float Q = epq[0][tid] + epq[1][tid] + epq[2][tid] + epq[3][tid];
        int slot = b * 32 + blockIdx.x;
        g_ps[0][slot * 256 + cob + tid] = S;
        g_pq[0][slot * 256 + cob + tid] = Q;
    }
}

// ---------------------------------------------------------------------------
// 1x1 conv tensor kernel (KIND 1: shortcut on g_xm; KIND 2: conv2 with fused
// silu(bn1) staging from g_y1). Same structure as before.
// ---------------------------------------------------------------------------
#define PA 136
#define PB 36
#define ABUF (32*PA)
#define BBUF2 (128*PB)
#define BUFF (ABUF + BBUF2)
#define SMEM_DYN (2 * BUFF * 4)

template <int KIND>
__global__ __launch_bounds__(256, 2) void k_tmma(void) {
    extern __shared__ float smf[];
    const uint32_t sbase = smem_u32(smf);
    const int tid = threadIdx.x;
    const int b = blockIdx.z;
    const int cob = blockIdx.y * 128;
    const int pxb = blockIdx.x * 128;

    const float* in   = (KIND == 2) ? g_y1 : g_xm;
    const float* wsrc = (KIND == 1) ? g_wscr : g_w2r;
    float* out        = (KIND == 1) ? g_sc : g_bb;

    const int l = tid & 31, wid = tid >> 5;
    const int warp_m = wid & 3, warp_n = wid >> 2;
    const int g = l >> 2, tg = l & 3;

    float d[2][8][4];
#pragma unroll
    for (int mt = 0; mt < 2; mt++)
#pragma unroll
        for (int nt = 0; nt < 8; nt++)
#pragma unroll
            for (int j = 0; j < 4; j++) d[mt][nt][j] = 0.f;

    auto stage = [&](int cc, int s) {
        uint32_t aB = sbase + (uint32_t)(s * BUFF) * 4u;
        uint32_t bB = aB + ABUF * 4u;
        int kb = cc * 32;
        if (KIND == 1) {
            const float* basep = in + ((size_t)(b * 256 + kb) << 12) + pxb;
#pragma unroll
            for (int it = 0; it < 4; it++) {
                int item = it * 256 + tid;
                int k = item >> 5, q = item & 31;
                CP16(aB + (uint32_t)(k * PA + q * 4) * 4u, basep + ((size_t)k << 12) + q * 4);
            }
        } else {
            const float* basep = in + ((size_t)(b * 256 + kb) << 12) + pxb;
            float* aF = smf + s * BUFF;
#pragma unroll
            for (int it = 0; it < 4; it++) {
                int item = it * 256 + tid;
                int k = item >> 5, q = item & 31;
                float4 v = *(const float4*)(basep + ((size_t)k << 12) + q * 4);
                float s1 = g_scale1[kb + k], t1 = g_bias1[kb + k];
                v.x = tf32r(silu_f(fmaf(s1, v.x, t1)));
                v.y = tf32r(silu_f(fmaf(s1, v.y, t1)));
                v.z = tf32r(silu_f(fmaf(s1, v.z, t1)));
                v.w = tf32r(silu_f(fmaf(s1, v.w, t1)));
                *(float4*)(aF + k * PA + q * 4) = v;
            }
        }
        {
            const float* wp = wsrc + (size_t)cob * 256 + kb;
#pragma unroll
            for (int it = 0; it < 4; it++) {
                int item = it * 256 + tid;
                int col = item >> 3, kq = item & 7;
                CP16(bB + (uint32_t)(col * PB + kq * 4) * 4u, wp + (size_t)col * 256 + kq * 4);
            }
        }
    };

    stage(0, 0);
    CP_COMMIT();

    for (int ch = 0; ch < 8; ch++) {
        if (ch + 1 < 8) {
            stage(ch + 1, (ch + 1) & 1);
            CP_COMMIT();
            CP_WAIT(1);
        } else {
            CP_WAIT(0);
        }
        __syncthreads();

        const float* As = smf + (ch & 1) * BUFF;
        const float* Bs = As + ABUF;
#pragma unroll
        for (int kt = 0; kt < 4; kt++) {
            int kk = kt * 8 + tg;
            uint32_t a[2][4];
#pragma unroll
            for (int mt = 0; mt < 2; mt++) {
                int m0 = warp_m * 32 + mt * 16 + g;
                a[mt][0] = __float_as_uint(As[kk * PA + m0]);
                a[mt][1] = __float_as_uint(As[kk * PA + m0 + 8]);
                a[mt][2] = __float_as_uint(As[(kk + 4) * PA + m0]);
                a[mt][3] = __float_as_uint(As[(kk + 4) * PA + m0 + 8]);
            }
#pragma unroll
            for (int nt = 0; nt < 8; nt++) {
                int n0 = warp_n * 64 + nt * 8 + g;
                uint32_t b0 = __float_as_uint(Bs[n0 * PB + kk]);
                uint32_t b1 = __float_as_uint(Bs[n0 * PB + kk + 4]);
                MMA8(d[0][nt], a[0], b0, b1);
                MMA8(d[1][nt], a[1], b0, b1);
            }
        }
        __syncthreads();
    }

    // ---- epilogue ----
#pragma unroll
    for (int mt = 0; mt < 2; mt++) {
        int px = pxb + warp_m * 32 + mt * 16 + g;
#pragma unroll
        for (int nt = 0; nt < 8; nt++) {
            int co = cob + warp_n * 64 + nt * 8 + tg * 2;
            float* o = out + (((size_t)(b * 256 + co)) << 12) + px;
            o[0]    = d[mt][nt][0];
            o[4096] = d[mt][nt][1];
            o[8]    = d[mt][nt][2];
            o[4104] = d[mt][nt][3];
        }
    }

    __shared__ float eps[4][128], epq[4][128];
#pragma unroll
    for (int nt = 0; nt < 8; nt++) {
        float s0 = d[0][nt][0] + d[0][nt][2] + d[1][nt][0] + d[1][nt][2];
        float s1 = d[0][nt][1] + d[0][nt][3] + d[1][nt][1] + d[1][nt][3];
        float q0 = d[0][nt][0] * d[0][nt][0] + d[0][nt][2] * d[0][nt][2]
                 + d[1][nt][0] * d[1][nt][0] + d[1][nt][2] * d[1][nt][2];
        float q1 = d[0][nt][1] * d[0][nt][1] + d[0][nt][3] * d[0][nt][3]
                 + d[1][nt][1] * d[1][nt][1] + d[1][nt][3] * d[1][nt][3];
#pragma unroll
        for (int of = 4; of <= 16; of <<= 1) {
            s0 += __shfl_xor_sync(0xffffffffu, s0, of);
            s1 += __shfl_xor_sync(0xffffffffu, s1, of);
            q0 += __shfl_xor_sync(0xffffffffu, q0, of);
            q1 += __shfl_xor_sync(0xffffffffu, q1, of);
        }
        if (l < 4) {
            int cl = warp_n * 64 + nt * 8 + l * 2;
            eps[warp_m][cl] = s0; eps[warp_m][cl + 1] = s1;
            epq[warp_m][cl] = q0; epq[warp_m][cl + 1] = q1;
        }
    }
    __syncthreads();
    if (tid < 128) {
        float S = eps[0][tid] + eps[1][tid] + eps[2][tid] + eps[3][tid];
        float Q = epq[0][tid] + epq[1][tid] + epq[2][tid] + epq[3][tid];
        int slot = b * 32 + blockIdx.x;
        g_ps[KIND][slot * 256 + cob + tid] = S;
        g_pq[KIND][slot * 256 + cob + tid] = Q;
    }
}

// ---------------------------------------------------------------------------
// Finalize BN stats from partials. k_fin01: modes 0 and 1 in one launch.
// ---------------------------------------------------------------------------
__device__ __forceinline__ void fin_one(int mode, int c, int t,
                                        const float* g, const float* be) {
    const float* PS = g_ps[mode];
    const float* PQ = g_pq[mode];
    float s = 0.f, q = 0.f;
    for (int i = t; i < 512; i += 128) { s += PS[i * 256 + c]; q += PQ[i * 256 + c]; }
    __shared__ float ss[128], sq[128];
    ss[t] = s; sq[t] = q;
    __syncthreads();
    for (int of = 64; of; of >>= 1) {
        if (t < of) { ss[t] += ss[t + of]; sq[t] += sq[t + of]; }
        __syncthreads();
    }
    if (t == 0) {
        const float inv_n = 1.0f / (16.0f * 4096.0f);
        float mean = ss[0] * inv_n;
        float var  = sq[0] * inv_n - mean * mean;
        float sc = g[c] * rsqrtf(var + 1e-5f);
        float bi = be[c] - mean * sc;
        if (mode == 0)      { g_scale1[c] = sc; g_bias1[c] = bi; }
        else if (mode == 1) { g_scaleS[c] = sc; g_biasS[c] = bi; }
        else                { g_scale2[c] = sc; g_bias2[c] = bi; }
    }
}

__global__ void k_fin01(const float* __restrict__ g1, const float* __restrict__ be1,
                        const float* __restrict__ gs, const float* __restrict__ bes) {
    int mode = blockIdx.x >> 8;
    int c = blockIdx.x & 255;
    if (mode == 0) fin_one(0, c, threadIdx.x, g1, be1);
    else           fin_one(1, c, threadIdx.x, gs, bes);
}

__global__ void k_fin(int mode, const float* __restrict__ g, const float* __restrict__ be) {
    fin_one(mode, blockIdx.x, threadIdx.x, g, be);
}

// ---------------------------------------------------------------------------
// Final: out = silu( bn2(bb) + bns(sc) )
// ---------------------------------------------------------------------------
__global__ void k_final(float* __restrict__ out) {
    int i4 = blockIdx.x * 256 + threadIdx.x;
    if (i4 >= NTOT / 4) return;
    int idx = i4 * 4;
    int c = (idx >> 12) & 255;
    float s2 = g_scale2[c], b2 = g_bias2[c];
    float ss = g_scaleS[c], bs = g_biasS[c];
    float4 vb = ((const float4*)g_bb)[i4];
    float4 vs = ((const float4*)g_sc)[i4];
    float4 r;
    r.x = silu_f(fmaf(s2, vb.x, b2) + fmaf(ss, vs.x, bs));
    r.y = silu_f(fmaf(s2, vb.y, b2) + fmaf(ss, vs.y, bs));
    r.z = silu_f(fmaf(s2, vb.z, b2) + fmaf(ss, vs.z, bs));
    r.w = silu_f(fmaf(s2, vb.w, b2) + fmaf(ss, vs.w, bs));
    ((float4*)out)[i4] = r;
}

// ---------------------------------------------------------------------------
extern "C" void kernel_launch(void* const* d_in, const int* in_sizes, int n_in,
                              void* d_out, int out_size) {
    const float* x     = (const float*)d_in[0];
    const float* dce   = (const float*)d_in[1];
    const float* w_dce = (const float*)d_in[2];
    const float* b_dce = (const float*)d_in[3];
    const float* w_ch  = (const float*)d_in[4];
    const float* w_sh  = (const float*)d_in[5];
    const float* b_sh  = (const float*)d_in[6];
    const float* w_ex  = (const float*)d_in[7];
    const float* b_ex  = (const float*)d_in[8];
    const float* w1    = (const float*)d_in[9];
    const float* g1    = (const float*)d_in[10];
    const float* be1   = (const float*)d_in[11];
    const float* w2    = (const float*)d_in[12];
    const float* g2    = (const float*)d_in[13];
    const float* be2   = (const float*)d_in[14];
    const float* wsc   = (const float*)d_in[15];
    const float* gs    = (const float*)d_in[16];
    const float* bes   = (const float*)d_in[17];

    cudaFuncSetAttribute(k_conv1,   cudaFuncAttributeMaxDynamicSharedMemorySize, SMEM_C1);
    cudaFuncSetAttribute(k_tmma<1>, cudaFuncAttributeMaxDynamicSharedMemorySize, SMEM_DYN);
    cudaFuncSetAttribute(k_tmma<2>, cudaFuncAttributeMaxDynamicSharedMemorySize, SMEM_DYN);

    dim3 gconv(32, 2, 16);

    k_wt<<<2304, 256>>>(w1);
    k_wround<<<256, 256>>>(wsc, w2);
    k_spatial<<<4096, 256>>>(x, w_ch);
    k_pool<<<16, 1024>>>(dce);
    k_gate1<<<dim3(8, 16), 128>>>(w_dce, b_dce);
    k_gate2<<<dim3(4, 16), 128>>>(w_sh, b_sh);
    k_gate3<<<dim3(8, 16), 128>>>(w_ex, b_ex);
    k_xm<<<16384, 256>>>(x);                    // g_xm = rna(x*mod)
    k_conv1<<<gconv, 256, SMEM_C1>>>();         // conv1 -> g_y1 (+bn1 partials)
    k_tmma<1><<<gconv, 256, SMEM_DYN>>>();      // shortcut -> g_sc (+bns partials)
    k_fin01<<<512, 128>>>(g1, be1, gs, bes);    // bn1 + bns scale/bias
    k_tmma<2><<<gconv, 256, SMEM_DYN>>>();      // conv2 (fused silu(bn1)) -> g_bb
    k_fin<<<256, 128>>>(2, g2, be2);            // bn2 scale/bias
    k_final<<<16384, 256>>>((float*)d_out);
}